// round 1
// baseline (speedup 1.0000x reference)
#include <cuda_runtime.h>
#include <cuda_bf16.h>
#include <cstdint>

// BoxCrop: crop -> aspect-preserving bilinear resize (long side = 336) -> pad(127)
// images: [64, 3, 768, 768] f32, boxes: [64, 4] i32 (XYWH), out: [64, 3, 336, 336] f32

#define O_SIZE 336
#define IMG_H 768
#define IMG_W 768
#define FILL_V 127.0f

__global__ void __launch_bounds__(256) boxcrop_kernel(
    const float* __restrict__ images,
    const int* __restrict__ boxes,
    float* __restrict__ out)
{
    const int b  = blockIdx.z;
    const int ox = blockIdx.x * blockDim.x + threadIdx.x;
    const int oy = blockIdx.y * blockDim.y + threadIdx.y;
    if (ox >= O_SIZE || oy >= O_SIZE) return;

    const int4 box = __ldg((const int4*)boxes + b);
    const int xb = box.x, yb = box.y, wb = box.z, hb = box.w;
    const float wf = (float)wb;
    const float hf = (float)hb;

    // Match JAX fp32 math: scale = 336/max; new_* = round-half-even(wf*scale)
    const float scale = 336.0f / fmaxf(wf, hf);
    const int new_w = (int)rintf(wf * scale);
    const int new_h = (int)rintf(hf * scale);
    const int pad_top  = (hb <  wb) ? (O_SIZE - new_h) / 2 : 0;
    const int pad_left = (hb >= wb) ? (O_SIZE - new_w) / 2 : 0;

    const int iy = oy - pad_top;
    const int ix = ox - pad_left;

    float* outp = out + ((size_t)b * 3) * (O_SIZE * O_SIZE) + oy * O_SIZE + ox;

    if (iy < 0 || iy >= new_h || ix < 0 || ix >= new_w) {
        outp[0]                     = FILL_V;
        outp[O_SIZE * O_SIZE]       = FILL_V;
        outp[2 * O_SIZE * O_SIZE]   = FILL_V;
        return;
    }

    // Match JAX order: ((i + 0.5) * len) / new_len
    const float src_y = (float)yb + (((float)iy + 0.5f) * hf) / (float)new_h - 0.5f;
    const float src_x = (float)xb + (((float)ix + 0.5f) * wf) / (float)new_w - 0.5f;

    const float y0f = floorf(src_y);
    const float x0f = floorf(src_x);
    const float wy = src_y - y0f;
    const float wx = src_x - x0f;

    const int ylo = yb, yhi = yb + hb - 1;
    const int xlo = xb, xhi = xb + wb - 1;
    const int y0 = min(max((int)y0f,     ylo), yhi);
    const int y1 = min(max((int)y0f + 1, ylo), yhi);
    const int x0 = min(max((int)x0f,     xlo), xhi);
    const int x1 = min(max((int)x0f + 1, xlo), xhi);

    const float* img = images + (size_t)b * 3 * (IMG_H * IMG_W);
    const int r0 = y0 * IMG_W;
    const int r1 = y1 * IMG_W;

    #pragma unroll
    for (int c = 0; c < 3; c++) {
        const float* p = img + (size_t)c * (IMG_H * IMG_W);
        const float v00 = __ldg(p + r0 + x0);
        const float v01 = __ldg(p + r0 + x1);
        const float v10 = __ldg(p + r1 + x0);
        const float v11 = __ldg(p + r1 + x1);
        const float top = v00 * (1.0f - wx) + v01 * wx;
        const float bot = v10 * (1.0f - wx) + v11 * wx;
        outp[c * (O_SIZE * O_SIZE)] = top * (1.0f - wy) + bot * wy;
    }
}

extern "C" void kernel_launch(void* const* d_in, const int* in_sizes, int n_in,
                              void* d_out, int out_size)
{
    const float* images = (const float*)d_in[0];
    const int*   boxes  = (const int*)d_in[1];
    float*       out    = (float*)d_out;

    dim3 block(32, 8, 1);
    dim3 grid((O_SIZE + 31) / 32, (O_SIZE + 7) / 8, 64);
    boxcrop_kernel<<<grid, block>>>(images, boxes, out);
}

// round 2
// speedup vs baseline: 1.0617x; 1.0617x over previous
#include <cuda_runtime.h>
#include <cuda_bf16.h>
#include <cstdint>

// BoxCrop: crop -> aspect-preserving bilinear resize (long side = 336) -> pad(127)
// images: [64, 3, 768, 768] f32, boxes: [64, 4] i32 (XYWH), out: [64, 3, 336, 336] f32
// 4 output pixels per thread along x; float4 stores; y-side math amortized.

#define O_SIZE   336
#define IMG_H    768
#define IMG_W    768
#define FILL_V   127.0f
#define GROUPS_X 84          // 336 / 4

__global__ void __launch_bounds__(256) boxcrop_kernel(
    const float* __restrict__ images,
    const int* __restrict__ boxes,
    float* __restrict__ out)
{
    const int b  = blockIdx.z;
    const int g  = blockIdx.x * blockDim.x + threadIdx.x;   // x-group index
    const int oy = blockIdx.y * blockDim.y + threadIdx.y;
    if (g >= GROUPS_X || oy >= O_SIZE) return;
    const int ox0 = g * 4;

    const int4 box = __ldg((const int4*)boxes + b);
    const int xb = box.x, yb = box.y, wb = box.z, hb = box.w;
    const float wf = (float)wb;
    const float hf = (float)hb;

    // Match JAX fp32 math: scale = 336/max; new_* = round-half-even(wf*scale)
    const float scale = 336.0f / fmaxf(wf, hf);
    const int new_w = (int)rintf(wf * scale);
    const int new_h = (int)rintf(hf * scale);
    const int pad_top  = (hb <  wb) ? (O_SIZE - new_h) / 2 : 0;
    const int pad_left = (hb >= wb) ? (O_SIZE - new_w) / 2 : 0;

    float4* outp = (float4*)(out + ((size_t)b * 3) * (O_SIZE * O_SIZE) + oy * O_SIZE + ox0);
    const int cstride4 = (O_SIZE * O_SIZE) / 4;   // float4 stride between channels

    const int iy  = oy  - pad_top;
    const int ix0 = ox0 - pad_left;

    const float4 fill4 = make_float4(FILL_V, FILL_V, FILL_V, FILL_V);

    // whole group out of the valid region -> pure fill, no loads
    if (iy < 0 || iy >= new_h || ix0 + 3 < 0 || ix0 >= new_w) {
        outp[0]            = fill4;
        outp[cstride4]     = fill4;
        outp[2 * cstride4] = fill4;
        return;
    }

    // ---- y side (once per thread) ----
    const float src_y = (float)yb + (((float)iy + 0.5f) * hf) / (float)new_h - 0.5f;
    const float y0f = floorf(src_y);
    const float wy  = src_y - y0f;
    const int ylo = yb, yhi = yb + hb - 1;
    const int y0 = min(max((int)y0f,     ylo), yhi);
    const int y1 = min(max((int)y0f + 1, ylo), yhi);
    const int r0 = y0 * IMG_W;
    const int r1 = y1 * IMG_W;
    const float owy = 1.0f - wy;

    // ---- x side (per pixel, indices reused across 3 channels) ----
    int   xi0[4], xi1[4];
    float wxv[4];
    bool  vld[4];
    const int xlo = xb, xhi = xb + wb - 1;
    const float new_wf = (float)new_w;
    #pragma unroll
    for (int j = 0; j < 4; j++) {
        const int ix = ix0 + j;
        vld[j] = (ix >= 0) & (ix < new_w);
        const float src_x = (float)xb + (((float)ix + 0.5f) * wf) / new_wf - 0.5f;
        const float x0f = floorf(src_x);
        wxv[j] = src_x - x0f;
        xi0[j] = min(max((int)x0f,     xlo), xhi);
        xi1[j] = min(max((int)x0f + 1, xlo), xhi);
    }

    const float* img = images + (size_t)b * 3 * (IMG_H * IMG_W);

    #pragma unroll
    for (int c = 0; c < 3; c++) {
        const float* p = img + (size_t)c * (IMG_H * IMG_W);
        float r[4];
        #pragma unroll
        for (int j = 0; j < 4; j++) {
            const float v00 = __ldg(p + r0 + xi0[j]);
            const float v01 = __ldg(p + r0 + xi1[j]);
            const float v10 = __ldg(p + r1 + xi0[j]);
            const float v11 = __ldg(p + r1 + xi1[j]);
            const float wx  = wxv[j];
            const float owx = 1.0f - wx;
            const float top = v00 * owx + v01 * wx;
            const float bot = v10 * owx + v11 * wx;
            const float val = top * owy + bot * wy;
            r[j] = vld[j] ? val : FILL_V;
        }
        outp[c * cstride4] = make_float4(r[0], r[1], r[2], r[3]);
    }
}

extern "C" void kernel_launch(void* const* d_in, const int* in_sizes, int n_in,
                              void* d_out, int out_size)
{
    const float* images = (const float*)d_in[0];
    const int*   boxes  = (const int*)d_in[1];
    float*       out    = (float*)d_out;

    dim3 block(32, 8, 1);
    dim3 grid((GROUPS_X + 31) / 32, (O_SIZE + 7) / 8, 64);
    boxcrop_kernel<<<grid, block>>>(images, boxes, out);
}